// round 12
// baseline (speedup 1.0000x reference)
#include <cuda_runtime.h>
#include <math.h>

#define N_SRC  80000
#define N_TGT  20000
#define E_NUM  80000
#define IN_DIM 128
#define DIM    64
#define EH     128
#define G3     192
#define NK     129
#define MAXU   2

typedef unsigned long long ull;

__device__ __forceinline__ ull pk2(float lo, float hi) {
    ull r; asm("mov.b64 %0, {%1,%2};" : "=l"(r) : "f"(lo), "f"(hi)); return r;
}
__device__ __forceinline__ void upk(ull v, float& lo, float& hi) {
    asm("mov.b64 {%0,%1}, %2;" : "=f"(lo), "=f"(hi) : "l"(v));
}
#define FMA_X2(d, a, b, c) asm("fma.rn.f32x2 %0, %1, %2, %3;" : "=l"(d) : "l"(a), "l"(b), "l"(c))
#define MUL_X2(d, a, b)    asm("mul.rn.f32x2 %0, %1, %2;"     : "=l"(d) : "l"(a), "l"(b))

__device__ __forceinline__ float sigm(float x)  { return __fdividef(1.0f, 1.0f + __expf(-x)); }
__device__ __forceinline__ float tanhx(float x) { return 1.0f - __fdividef(2.0f, 1.0f + __expf(2.0f * x)); }

// ---------------- scratch ------------------------------------------------
__device__ float g_h0[N_SRC * DIM];
__device__ float g_M[NK][DIM * DIM];
__device__ float g_P[NK][DIM * DIM];
__device__ ull   g_Td[NK][DIM * 32 * 4]; // [i][lane]{Mlo_dup,Mhi_dup,Plo_dup,Phi_dup}
__device__ float g_thr[EH];
__device__ unsigned char g_act[NK][EH];
__device__ int   g_kedge[E_NUM];
__device__ float g_aedge[E_NUM];
__device__ int   g_used[NK];
__device__ int   g_slotmap[NK];
__device__ int   g_slotk[MAXU];
__device__ int   g_usedlist[NK];
__device__ int   g_usedcnt;
__device__ int   g_nslots;
__device__ int   g_deg[N_TGT];
__device__ int   g_off[N_TGT];
__device__ int   g_cur[N_TGT];
__device__ uint2 g_ce[E_NUM];            // {word, float-bits a}
// weight tables
__device__ ull   g_W0p[DIM * 64];        // [o][ip] = pk2(W0[o,2ip], W0[o,2ip+1])
__device__ ull   g_Wih_q[DIM * 3 * 64];  // paired-gate dup tables (ulonglong2 loads)
__device__ ull   g_Whh_q[DIM * 3 * 64];
__device__ ull   g_Wr_q[DIM * 64];
__device__ ull   g_W1q[DIM * 64];
__device__ ull   g_W2q[DIM * 64];

// ================= kA: zero + prep + setup (merged) ======================
__global__ __launch_bounds__(256) void kA(const float* __restrict__ W0,
                                          const float* __restrict__ Wih,
                                          const float* __restrict__ Whh,
                                          const float* __restrict__ Wr,
                                          const float* __restrict__ W1,
                                          const float* __restrict__ W2,
                                          const float* __restrict__ A1,
                                          const float* __restrict__ c1) {
    int b = blockIdx.x;
    int t = threadIdx.x;
    if (b < 79) {                               // zero
        int idx = b * 256 + t;
        if (idx < N_TGT) g_deg[idx] = 0;
        if (idx < NK)    g_used[idx] = 0;
        return;
    }
    if (b < 127) {                              // prep
        int idx = (b - 79) * 256 + t;
        if (idx < DIM * 64) {                   // W0 i-pairs: o 0..63, ip 0..63
            int o = idx >> 6, ip = idx & 63;
            g_W0p[idx] = pk2(W0[o * IN_DIM + 2 * ip], W0[o * IN_DIM + 2 * ip + 1]);
        }
        if (idx < DIM * G3) {
            int o = idx / G3, g = idx % G3;
            int l = g & 31, tt = g >> 5;
            int pos = ((o * 3 + (tt >> 1)) * 32 + l) * 2 + (tt & 1);
            float wi = Wih[g * DIM + o]; g_Wih_q[pos] = pk2(wi, wi);
            float wh = Whh[g * DIM + o]; g_Whh_q[pos] = pk2(wh, wh);
        }
        if (idx < DIM * DIM) {
            int i = idx / DIM, o = idx % DIM;
            int pos = (i * 32 + (o & 31)) * 2 + (o >> 5);
            float wr = Wr[i * DIM + o];  g_Wr_q[pos] = pk2(wr, wr);
            float w1 = W1[o * DIM + i];  g_W1q[pos] = pk2(w1, w1);
            float w2 = W2[o * DIM + i];  g_W2q[pos] = pk2(w2, w2);
        }
        return;
    }
    // setup (1 block, threads < 128)
    __shared__ float ts[EH], sorted[EH];
    if (t >= EH) return;
    int j = t;
    float s = A1[j];
    float c = c1[j];
    float th = (s != 0.0f) ? (-c / s) : 2.0e30f;
    ts[j] = th;
    __syncwarp();
    __syncthreads();
    int rank = 0;
    for (int k = 0; k < EH; k++) {
        float tk = ts[k];
        rank += (tk < th) || (tk == th && k < j);
    }
    sorted[rank] = th;
    __syncthreads();
    g_thr[j] = sorted[j];
    const float BIGT = 1.0e29f;
    for (int k = 0; k < NK; k++) {
        float left  = (k > 0)  ? sorted[k - 1] : -2.0e30f;
        float right = (k < EH) ? sorted[k]     :  2.0e30f;
        bool linf = (left <= -BIGT), rinf = (right >= BIGT);
        float rep;
        if (linf && rinf)      rep = 0.0f;
        else if (linf)         rep = right - 1.0f;
        else if (rinf)         rep = left + 1.0f;
        else                   rep = 0.5f * (left + right);
        g_act[k][j] = (s * rep + c > 0.0f) ? 1 : 0;
    }
}

// ================= kB: h0 + edgek (merged) ===============================
#define H0_BLOCKS (N_SRC / 32)   // 2500
__global__ __launch_bounds__(256) void kB(const float* __restrict__ x,
                                          const float* __restrict__ b0,
                                          const int* __restrict__ eids,
                                          const float* __restrict__ ew,
                                          const int* __restrict__ edst) {
    __shared__ float sthr[EH];
    if (blockIdx.x < H0_BLOCKS) {
        // ---- h0 = relu(x @ W0^T + b0), i-pair packed (mov-free) ----
        int o  = threadIdx.x & 63;          // output
        int rg = threadIdx.x >> 6;          // 0..3 row groups
        int row0 = blockIdx.x * 32 + rg * 8;
        ull acc[8] = {0ull, 0ull, 0ull, 0ull, 0ull, 0ull, 0ull, 0ull};
        const ulonglong2* __restrict__ W = reinterpret_cast<const ulonglong2*>(g_W0p + o * 64);
#pragma unroll 4
        for (int ii = 0; ii < 32; ii++) {
            ulonglong2 wv = __ldg(&W[ii]);  // dims 4ii..4ii+3 as 2 packed pairs
#pragma unroll
            for (int r = 0; r < 8; r++) {
                ulonglong2 xv = *reinterpret_cast<const ulonglong2*>(
                    x + (size_t)(row0 + r) * IN_DIM + 4 * ii);
                FMA_X2(acc[r], xv.x, wv.x, acc[r]);
                FMA_X2(acc[r], xv.y, wv.y, acc[r]);
            }
        }
        float b = b0[o];
#pragma unroll
        for (int r = 0; r < 8; r++) {
            float lo, hi;
            upk(acc[r], lo, hi);
            g_h0[(size_t)(row0 + r) * DIM + o] = fmaxf(lo + hi + b, 0.0f);
        }
    } else {
        if (threadIdx.x < EH) sthr[threadIdx.x] = g_thr[threadIdx.x];
        __syncthreads();
        int e = (blockIdx.x - H0_BLOCKS) * 256 + threadIdx.x;
        if (e >= E_NUM) return;
        float a = ew[eids[e]];
        int k = 0;
#pragma unroll
        for (int j = 0; j < EH; j++) k += (sthr[j] < a) ? 1 : 0;
        g_kedge[e] = k;
        g_aedge[e] = a;
        g_used[k]  = 1;
        atomicAdd(&g_deg[edst[e]], 1);
    }
}

// ================= kC: scan (block 0) + slots (block 1) ==================
__global__ __launch_bounds__(1024) void kC() {
    if (blockIdx.x == 0) {
        __shared__ int wsum[32];
        int t = threadIdx.x;
        int start = t * 20;
        int s = 0;
#pragma unroll
        for (int i = 0; i < 20; i++) {
            int idx = start + i;
            if (idx < N_TGT) s += g_deg[idx];
        }
        int lane = t & 31, wid = t >> 5;
        int v = s;
#pragma unroll
        for (int off = 1; off < 32; off <<= 1) {
            int n = __shfl_up_sync(0xffffffffu, v, off);
            if (lane >= off) v += n;
        }
        if (lane == 31) wsum[wid] = v;
        __syncthreads();
        if (wid == 0) {
            int w = wsum[lane];
#pragma unroll
            for (int off = 1; off < 32; off <<= 1) {
                int n = __shfl_up_sync(0xffffffffu, w, off);
                if (lane >= off) w += n;
            }
            wsum[lane] = w;
        }
        __syncthreads();
        int excl = (v - s) + ((wid > 0) ? wsum[wid - 1] : 0);
        int run = excl;
#pragma unroll
        for (int i = 0; i < 20; i++) {
            int idx = start + i;
            if (idx < N_TGT) {
                g_off[idx] = run;
                g_cur[idx] = run;
                run += g_deg[idx];
            }
        }
    } else {
        if (threadIdx.x == 0) {
            int ns = 0;
            for (int k = 0; k < NK; k++) {
                g_slotmap[k] = -1;
                if (g_used[k]) {
                    if (ns < MAXU) { g_slotmap[k] = ns; g_slotk[ns] = k; }
                    g_usedlist[ns] = k;
                    ns++;
                }
            }
            g_usedcnt = ns;
            g_nslots = (ns < MAXU) ? ns : MAXU;
        }
    }
}

// ================= kD: csr + tables (merged) =============================
#define CSR_BLOCKS 313
#define TB_Y 2
__global__ __launch_bounds__(256) void kD(const int* __restrict__ esrc,
                                          const int* __restrict__ edst,
                                          const float* __restrict__ A1,
                                          const float* __restrict__ c1,
                                          const float* __restrict__ A2,
                                          const float* __restrict__ c2) {
    __shared__ float hs[EH], h2s[EH];
    if (blockIdx.x < CSR_BLOCKS) {
        int e = blockIdx.x * 256 + threadIdx.x;
        if (e >= E_NUM) return;
        int dst = edst[e];
        int pos = atomicAdd(&g_cur[dst], 1);
        int k = g_kedge[e];
        int sm = g_slotmap[k];
        unsigned sc = (sm >= 0) ? (unsigned)sm : 7u;
        uint2 ce;
        ce.x = (unsigned)esrc[e] | ((unsigned)k << 17) | (sc << 25);
        ce.y = __float_as_uint(g_aedge[e]);
        g_ce[pos] = ce;
    } else {
        int bb = blockIdx.x - CSR_BLOCKS;
        int bx = bb & 511;
        int by = bb >> 9;
        int cnt = g_usedcnt;
        int t = threadIdx.x;
        for (int y = by; y < cnt; y += TB_Y) {
            int k = g_usedlist[y];
            __syncthreads();
            if (t < EH) {
                float a = g_act[k][t] ? 1.0f : 0.0f;
                hs[t]  = A1[t] * a;
                h2s[t] = c1[t] * a;
            }
            __syncthreads();
            int w = t >> 5, l = t & 31;
            int io = bx * 8 + w;
            const float4 av = *reinterpret_cast<const float4*>(A2 + (size_t)io * EH + l * 4);
            float m = av.x * hs[l * 4] + av.y * hs[l * 4 + 1] + av.z * hs[l * 4 + 2] + av.w * hs[l * 4 + 3];
            float p = av.x * h2s[l * 4] + av.y * h2s[l * 4 + 1] + av.z * h2s[l * 4 + 2] + av.w * h2s[l * 4 + 3];
#pragma unroll
            for (int off = 16; off > 0; off >>= 1) {
                m += __shfl_down_sync(0xffffffffu, m, off);
                p += __shfl_down_sync(0xffffffffu, p, off);
            }
            if (l == 0) {
                float pv = c2[io] + p;
                g_M[k][io] = m;
                g_P[k][io] = pv;
                int i = io >> 6, o = io & 63;
                int base = (i * 32 + (o & 31)) * 4 + (o >> 5);
                g_Td[k][base]     = pk2(m, m);
                g_Td[k][base + 2] = pk2(pv, pv);
            }
        }
    }
}

// ================= k_tail: gather+transform+conv+gi+GRU+head =============
__global__ __launch_bounds__(256, 2) void k_tail(const float* __restrict__ b_conv,
                                                 const float* __restrict__ b_ih,
                                                 const float* __restrict__ b_hh,
                                                 const float* __restrict__ b1,
                                                 const float* __restrict__ b2,
                                                 float* __restrict__ out) {
    __shared__ float st[8][64 * 16];
    int wid = threadIdx.x >> 5;
    int l   = threadIdx.x & 31;
    int gw  = (blockIdx.x * 256 + threadIdx.x) >> 5;
    int t0  = gw * 4;
    float* sw = st[wid];
    int ns = g_nslots;

    int offv[4], degv[4];
#pragma unroll
    for (int q = 0; q < 4; q++) { offv[q] = g_off[t0 + q]; degv[q] = g_deg[t0 + q]; }
    int dmax = max(max(degv[0], degv[1]), max(degv[2], degv[3]));

    // pair-layout sums: lane l holds dims (2l, 2l+1) packed
    ull S1p[MAXU][4], S0p[MAXU][4];
#pragma unroll
    for (int s = 0; s < MAXU; s++)
#pragma unroll
        for (int q = 0; q < 4; q++) { S1p[s][q] = 0ull; S0p[s][q] = 0ull; }
    float fbA[4] = {0, 0, 0, 0}, fbB[4] = {0, 0, 0, 0};

    // ---- gather: depth-2 meta, depth-1 xs software pipeline ----
    uint2 mA[4], mB[4];
    float2 xA[4];
#pragma unroll
    for (int q = 0; q < 4; q++) if (degv[q] > 0) mA[q] = __ldg(&g_ce[offv[q]]);
#pragma unroll
    for (int q = 0; q < 4; q++) if (degv[q] > 1) mB[q] = __ldg(&g_ce[offv[q] + 1]);
#pragma unroll
    for (int q = 0; q < 4; q++)
        if (degv[q] > 0) {
            int s = (int)(mA[q].x & 0x1FFFFu);
            xA[q] = __ldg(reinterpret_cast<const float2*>(g_h0 + (size_t)s * DIM + 2 * l));
        }
    for (int j = 0; j < dmax; j++) {
        uint2 mC[4]; float2 xB[4];
#pragma unroll
        for (int q = 0; q < 4; q++)
            if (j + 2 < degv[q]) mC[q] = __ldg(&g_ce[offv[q] + j + 2]);
#pragma unroll
        for (int q = 0; q < 4; q++)
            if (j + 1 < degv[q]) {
                int s = (int)(mB[q].x & 0x1FFFFu);
                xB[q] = __ldg(reinterpret_cast<const float2*>(g_h0 + (size_t)s * DIM + 2 * l));
            }
#pragma unroll
        for (int q = 0; q < 4; q++) {
            if (j < degv[q]) {
                unsigned w = mA[q].x;
                float a = __uint_as_float(mA[q].y);
                unsigned sc = w >> 25;
                ull xsp = pk2(xA[q].x, xA[q].y);
                ull axp;
                MUL_X2(axp, xsp, pk2(a, a));
#pragma unroll
                for (int s = 0; s < MAXU; s++) {
                    float sel = (sc == (unsigned)s) ? 1.0f : 0.0f;
                    ull selp = pk2(sel, sel);
                    FMA_X2(S1p[s][q], axp, selp, S1p[s][q]);
                    FMA_X2(S0p[s][q], xsp, selp, S0p[s][q]);
                }
                if (sc == 7u) {                  // exact fallback (rare)
                    int k = (int)((w >> 17) & 0xFFu);
                    const float* __restrict__ M = g_M[k];
                    const float* __restrict__ P = g_P[k];
#pragma unroll 8
                    for (int i = 0; i < DIM; i++) {
                        float xi  = __shfl_sync(0xffffffffu, (i & 1) ? xA[q].y : xA[q].x, i >> 1);
                        float axi = a * xi;
                        fbA[q] += axi * M[i * DIM + l]      + xi * P[i * DIM + l];
                        fbB[q] += axi * M[i * DIM + 32 + l] + xi * P[i * DIM + 32 + l];
                    }
                }
            }
        }
#pragma unroll
        for (int q = 0; q < 4; q++) { mA[q] = mB[q]; mB[q] = mC[q]; xA[q] = xB[q]; }
    }

    // ---- stage S dim-major: sw[dim*16 + s*8 + {S1:0..3, S0:4..7}] ----
#pragma unroll
    for (int s = 0; s < MAXU; s++) {
        float x1[4], y1[4], x0[4], y0[4];
#pragma unroll
        for (int q = 0; q < 4; q++) {
            upk(S1p[s][q], x1[q], y1[q]);
            upk(S0p[s][q], x0[q], y0[q]);
        }
        *reinterpret_cast<float4*>(sw + (2 * l) * 16 + s * 8)         = make_float4(x1[0], x1[1], x1[2], x1[3]);
        *reinterpret_cast<float4*>(sw + (2 * l) * 16 + s * 8 + 4)     = make_float4(x0[0], x0[1], x0[2], x0[3]);
        *reinterpret_cast<float4*>(sw + (2 * l + 1) * 16 + s * 8)     = make_float4(y1[0], y1[1], y1[2], y1[3]);
        *reinterpret_cast<float4*>(sw + (2 * l + 1) * 16 + s * 8 + 4) = make_float4(y0[0], y0[1], y0[2], y0[3]);
    }
    __syncwarp();

    // ---- transform (dup-packed tables, ull2 smem reads: mov-free) ----
    ull accA[2], accB[2];
    accA[0] = pk2(fbA[0], fbA[1]); accA[1] = pk2(fbA[2], fbA[3]);
    accB[0] = pk2(fbB[0], fbB[1]); accB[1] = pk2(fbB[2], fbB[3]);
#pragma unroll
    for (int s = 0; s < MAXU; s++) {
        if (s >= ns) break;
        const ulonglong2* __restrict__ Td = reinterpret_cast<const ulonglong2*>(g_Td[g_slotk[s]]);
#pragma unroll 4
        for (int i = 0; i < DIM; i++) {
            ulonglong2 sv1 = *reinterpret_cast<const ulonglong2*>(sw + i * 16 + s * 8);
            ulonglong2 sv0 = *reinterpret_cast<const ulonglong2*>(sw + i * 16 + s * 8 + 4);
            ulonglong2 tA = __ldg(&Td[(i * 32 + l) * 2]);     // {Mlo_dup, Mhi_dup}
            ulonglong2 tB = __ldg(&Td[(i * 32 + l) * 2 + 1]); // {Plo_dup, Phi_dup}
            FMA_X2(accA[0], sv1.x, tA.x, accA[0]);
            FMA_X2(accA[1], sv1.y, tA.x, accA[1]);
            FMA_X2(accA[0], sv0.x, tB.x, accA[0]);
            FMA_X2(accA[1], sv0.y, tB.x, accA[1]);
            FMA_X2(accB[0], sv1.x, tA.y, accB[0]);
            FMA_X2(accB[1], sv1.y, tA.y, accB[1]);
            FMA_X2(accB[0], sv0.x, tB.y, accB[0]);
            FMA_X2(accB[1], sv0.y, tB.y, accB[1]);
        }
    }

    // ---- divide by counts ----
    {
        float i0 = __fdividef(1.0f, fmaxf((float)degv[0], 1.0f));
        float i1 = __fdividef(1.0f, fmaxf((float)degv[1], 1.0f));
        float i2 = __fdividef(1.0f, fmaxf((float)degv[2], 1.0f));
        float i3 = __fdividef(1.0f, fmaxf((float)degv[3], 1.0f));
        float v0, v1;
        upk(accA[0], v0, v1); accA[0] = pk2(v0 * i0, v1 * i1);
        upk(accA[1], v0, v1); accA[1] = pk2(v0 * i2, v1 * i3);
        upk(accB[0], v0, v1); accB[0] = pk2(v0 * i0, v1 * i1);
        upk(accB[1], v0, v1); accB[1] = pk2(v0 * i2, v1 * i3);
    }

    // ---- x_tgt pair-load + dim-major staging + conv root matvec ----
    float2 xtp[4];
#pragma unroll
    for (int q = 0; q < 4; q++)
        xtp[q] = *reinterpret_cast<const float2*>(g_h0 + (size_t)(t0 + q) * DIM + 2 * l);
    __syncwarp();
    *reinterpret_cast<float4*>(sw + (2 * l) * 4)     = make_float4(xtp[0].x, xtp[1].x, xtp[2].x, xtp[3].x);
    *reinterpret_cast<float4*>(sw + (2 * l + 1) * 4) = make_float4(xtp[0].y, xtp[1].y, xtp[2].y, xtp[3].y);
    __syncwarp();
#pragma unroll 4
    for (int i = 0; i < DIM; i++) {
        ulonglong2 xv = *reinterpret_cast<const ulonglong2*>(sw + i * 4);
        ulonglong2 wv = *reinterpret_cast<const ulonglong2*>(g_Wr_q + (i * 32 + l) * 2);
        FMA_X2(accA[0], xv.x, wv.x, accA[0]); FMA_X2(accA[1], xv.y, wv.x, accA[1]);
        FMA_X2(accB[0], xv.x, wv.y, accB[0]); FMA_X2(accB[1], xv.y, wv.y, accB[1]);
    }
    // x_tgt in l/32+l layout (for GRU h-init), read back from dim-major smem
    float xt0[4], xt1[4];
    {
        float4 v = *reinterpret_cast<const float4*>(sw + l * 4);
        xt0[0] = v.x; xt0[1] = v.y; xt0[2] = v.z; xt0[3] = v.w;
        float4 u = *reinterpret_cast<const float4*>(sw + (32 + l) * 4);
        xt1[0] = u.x; xt1[1] = u.y; xt1[2] = u.z; xt1[3] = u.w;
    }
    // m = relu(acc + b_conv) in l/32+l layout
    float m0[4], m1[4];
    {
        float bc0 = b_conv[l], bc1 = b_conv[32 + l];
        float v0, v1;
        upk(accA[0], v0, v1); m0[0] = fmaxf(v0 + bc0, 0.0f); m0[1] = fmaxf(v1 + bc0, 0.0f);
        upk(accA[1], v0, v1); m0[2] = fmaxf(v0 + bc0, 0.0f); m0[3] = fmaxf(v1 + bc0, 0.0f);
        upk(accB[0], v0, v1); m1[0] = fmaxf(v0 + bc1, 0.0f); m1[1] = fmaxf(v1 + bc1, 0.0f);
        upk(accB[1], v0, v1); m1[2] = fmaxf(v0 + bc1, 0.0f); m1[3] = fmaxf(v1 + bc1, 0.0f);
    }

    // ---- gi = m @ W_ih^T + b_ih ----
    __syncwarp();
    *reinterpret_cast<float4*>(sw + l * 4)        = make_float4(m0[0], m0[1], m0[2], m0[3]);
    *reinterpret_cast<float4*>(sw + (32 + l) * 4) = make_float4(m1[0], m1[1], m1[2], m1[3]);
    __syncwarp();
    ull gip[6][2];
#pragma unroll
    for (int t = 0; t < 6; t++) { gip[t][0] = 0ull; gip[t][1] = 0ull; }
#pragma unroll 2
    for (int o = 0; o < DIM; o++) {
        ulonglong2 mvp = *reinterpret_cast<const ulonglong2*>(sw + o * 4);
#pragma unroll
        for (int tp = 0; tp < 3; tp++) {
            ulonglong2 wv = *reinterpret_cast<const ulonglong2*>(g_Wih_q + ((o * 3 + tp) * 32 + l) * 2);
            FMA_X2(gip[2 * tp][0],     mvp.x, wv.x, gip[2 * tp][0]);
            FMA_X2(gip[2 * tp][1],     mvp.y, wv.x, gip[2 * tp][1]);
            FMA_X2(gip[2 * tp + 1][0], mvp.x, wv.y, gip[2 * tp + 1][0]);
            FMA_X2(gip[2 * tp + 1][1], mvp.y, wv.y, gip[2 * tp + 1][1]);
        }
    }
    float gi[6][4];
#pragma unroll
    for (int t = 0; t < 6; t++) {
        float bi = b_ih[l + 32 * t];
        float v0, v1;
        upk(gip[t][0], v0, v1); gi[t][0] = v0 + bi; gi[t][1] = v1 + bi;
        upk(gip[t][1], v0, v1); gi[t][2] = v0 + bi; gi[t][3] = v1 + bi;
    }

    // ---- GRU x3 (h init = x_tgt) ----
    float h0r[4], h1r[4];
#pragma unroll
    for (int q = 0; q < 4; q++) { h0r[q] = xt0[q]; h1r[q] = xt1[q]; }
    float bh[6];
#pragma unroll
    for (int t = 0; t < 6; t++) bh[t] = b_hh[l + 32 * t];

    for (int step = 0; step < 3; step++) {
        __syncwarp();
        *reinterpret_cast<float4*>(sw + l * 4)        = make_float4(h0r[0], h0r[1], h0r[2], h0r[3]);
        *reinterpret_cast<float4*>(sw + (32 + l) * 4) = make_float4(h1r[0], h1r[1], h1r[2], h1r[3]);
        __syncwarp();
        ull ghp[6][2];
#pragma unroll
        for (int t = 0; t < 6; t++) {
            ghp[t][0] = pk2(bh[t], bh[t]);
            ghp[t][1] = ghp[t][0];
        }
#pragma unroll 2
        for (int i = 0; i < DIM; i++) {
            ulonglong2 hvp = *reinterpret_cast<const ulonglong2*>(sw + i * 4);
#pragma unroll
            for (int tp = 0; tp < 3; tp++) {
                ulonglong2 wv = *reinterpret_cast<const ulonglong2*>(g_Whh_q + ((i * 3 + tp) * 32 + l) * 2);
                FMA_X2(ghp[2 * tp][0],     hvp.x, wv.x, ghp[2 * tp][0]);
                FMA_X2(ghp[2 * tp][1],     hvp.y, wv.x, ghp[2 * tp][1]);
                FMA_X2(ghp[2 * tp + 1][0], hvp.x, wv.y, ghp[2 * tp + 1][0]);
                FMA_X2(ghp[2 * tp + 1][1], hvp.y, wv.y, ghp[2 * tp + 1][1]);
            }
        }
#pragma unroll
        for (int q = 0; q < 4; q++) {
            float ghv[6];
#pragma unroll
            for (int t = 0; t < 6; t++) {
                float lo, hi;
                upk(ghp[t][q >> 1], lo, hi);
                ghv[t] = (q & 1) ? hi : lo;
            }
            float rr0 = sigm(gi[0][q] + ghv[0]);
            float rr1 = sigm(gi[1][q] + ghv[1]);
            float zz0 = sigm(gi[2][q] + ghv[2]);
            float zz1 = sigm(gi[3][q] + ghv[3]);
            float nn0 = tanhx(gi[4][q] + rr0 * ghv[4]);
            float nn1 = tanhx(gi[5][q] + rr1 * ghv[5]);
            h0r[q] = (1.0f - zz0) * nn0 + zz0 * h0r[q];
            h1r[q] = (1.0f - zz1) * nn1 + zz1 * h1r[q];
        }
    }

    // ---- head layer 1: a = relu(h @ W1^T + b1) ----
    __syncwarp();
    *reinterpret_cast<float4*>(sw + l * 4)        = make_float4(h0r[0], h0r[1], h0r[2], h0r[3]);
    *reinterpret_cast<float4*>(sw + (32 + l) * 4) = make_float4(h1r[0], h1r[1], h1r[2], h1r[3]);
    __syncwarp();
    ull aA01 = 0ull, aA23 = 0ull, aB01 = 0ull, aB23 = 0ull;
#pragma unroll 4
    for (int i = 0; i < DIM; i++) {
        ulonglong2 hvp = *reinterpret_cast<const ulonglong2*>(sw + i * 4);
        ulonglong2 wv = *reinterpret_cast<const ulonglong2*>(g_W1q + (i * 32 + l) * 2);
        FMA_X2(aA01, hvp.x, wv.x, aA01); FMA_X2(aA23, hvp.y, wv.x, aA23);
        FMA_X2(aB01, hvp.x, wv.y, aB01); FMA_X2(aB23, hvp.y, wv.y, aB23);
    }
    float a0[4], a1[4];
    {
        float bb0 = b1[l], bb1 = b1[32 + l];
        float v0, v1;
        upk(aA01, v0, v1); a0[0] = fmaxf(v0 + bb0, 0.0f); a0[1] = fmaxf(v1 + bb0, 0.0f);
        upk(aA23, v0, v1); a0[2] = fmaxf(v0 + bb0, 0.0f); a0[3] = fmaxf(v1 + bb0, 0.0f);
        upk(aB01, v0, v1); a1[0] = fmaxf(v0 + bb1, 0.0f); a1[1] = fmaxf(v1 + bb1, 0.0f);
        upk(aB23, v0, v1); a1[2] = fmaxf(v0 + bb1, 0.0f); a1[3] = fmaxf(v1 + bb1, 0.0f);
    }

    // ---- head layer 2: out = a @ W2^T + b2 ----
    __syncwarp();
    *reinterpret_cast<float4*>(sw + l * 4)        = make_float4(a0[0], a0[1], a0[2], a0[3]);
    *reinterpret_cast<float4*>(sw + (32 + l) * 4) = make_float4(a1[0], a1[1], a1[2], a1[3]);
    __syncwarp();
    ull cA01 = 0ull, cA23 = 0ull, cB01 = 0ull, cB23 = 0ull;
#pragma unroll 4
    for (int i = 0; i < DIM; i++) {
        ulonglong2 avp = *reinterpret_cast<const ulonglong2*>(sw + i * 4);
        ulonglong2 wv = *reinterpret_cast<const ulonglong2*>(g_W2q + (i * 32 + l) * 2);
        FMA_X2(cA01, avp.x, wv.x, cA01); FMA_X2(cA23, avp.y, wv.x, cA23);
        FMA_X2(cB01, avp.x, wv.y, cB01); FMA_X2(cB23, avp.y, wv.y, cB23);
    }
    {
        float ob0 = b2[l], ob1 = b2[32 + l];
        float v0, v1;
        upk(cA01, v0, v1);
        out[(size_t)(t0 + 0) * DIM + l] = v0 + ob0;
        out[(size_t)(t0 + 1) * DIM + l] = v1 + ob0;
        upk(cA23, v0, v1);
        out[(size_t)(t0 + 2) * DIM + l] = v0 + ob0;
        out[(size_t)(t0 + 3) * DIM + l] = v1 + ob0;
        upk(cB01, v0, v1);
        out[(size_t)(t0 + 0) * DIM + 32 + l] = v0 + ob1;
        out[(size_t)(t0 + 1) * DIM + 32 + l] = v1 + ob1;
        upk(cB23, v0, v1);
        out[(size_t)(t0 + 2) * DIM + 32 + l] = v0 + ob1;
        out[(size_t)(t0 + 3) * DIM + 32 + l] = v1 + ob1;
    }
}

// ---------------- launch ---------------------------------------------------
extern "C" void kernel_launch(void* const* d_in, const int* in_sizes, int n_in,
                              void* d_out, int out_size) {
    const float* x        = (const float*)d_in[0];
    const int*   edge_src = (const int*)d_in[2];
    const int*   edge_dst = (const int*)d_in[3];
    const int*   edge_ids = (const int*)d_in[4];
    const float* edge_w   = (const float*)d_in[5];
    const float* W0       = (const float*)d_in[6];
    const float* b0       = (const float*)d_in[7];
    const float* A1       = (const float*)d_in[8];
    const float* c1       = (const float*)d_in[9];
    const float* A2       = (const float*)d_in[10];
    const float* c2       = (const float*)d_in[11];
    const float* W_root   = (const float*)d_in[12];
    const float* b_conv   = (const float*)d_in[13];
    const float* W_ih     = (const float*)d_in[14];
    const float* W_hh     = (const float*)d_in[15];
    const float* b_ih     = (const float*)d_in[16];
    const float* b_hh     = (const float*)d_in[17];
    const float* W1       = (const float*)d_in[18];
    const float* b1       = (const float*)d_in[19];
    const float* W2       = (const float*)d_in[20];
    const float* b2       = (const float*)d_in[21];
    float* out = (float*)d_out;

    kA<<<128, 256>>>(W0, W_ih, W_hh, W_root, W1, W2, A1, c1);
    kB<<<H0_BLOCKS + 313, 256>>>(x, b0, edge_ids, edge_w, edge_dst);
    kC<<<2, 1024>>>();
    kD<<<CSR_BLOCKS + 512 * TB_Y, 256>>>(edge_src, edge_dst, A1, c1, A2, c2);
    k_tail<<<N_TGT / 4 / 8, 256>>>(b_conv, b_ih, b_hh, b1, b2, out);
}

// round 15
// speedup vs baseline: 1.2514x; 1.2514x over previous
#include <cuda_runtime.h>
#include <math.h>

#define N_SRC  80000
#define N_TGT  20000
#define E_NUM  80000
#define IN_DIM 128
#define DIM    64
#define EH     128
#define G3     192
#define NK     129
#define MAXU   2

typedef unsigned long long ull;

__device__ __forceinline__ ull pk2(float lo, float hi) {
    ull r; asm("mov.b64 %0, {%1,%2};" : "=l"(r) : "f"(lo), "f"(hi)); return r;
}
__device__ __forceinline__ void upk(ull v, float& lo, float& hi) {
    asm("mov.b64 {%0,%1}, %2;" : "=f"(lo), "=f"(hi) : "l"(v));
}
#define FMA_X2(d, a, b, c) asm("fma.rn.f32x2 %0, %1, %2, %3;" : "=l"(d) : "l"(a), "l"(b), "l"(c))
#define MUL_X2(d, a, b)    asm("mul.rn.f32x2 %0, %1, %2;"     : "=l"(d) : "l"(a), "l"(b))

__device__ __forceinline__ float sigm(float x)  { return __fdividef(1.0f, 1.0f + __expf(-x)); }
__device__ __forceinline__ float tanhx(float x) { return 1.0f - __fdividef(2.0f, 1.0f + __expf(2.0f * x)); }

// ---------------- scratch ------------------------------------------------
__device__ float g_h0[N_SRC * DIM];
__device__ float g_M[NK][DIM * DIM];
__device__ float g_P[NK][DIM * DIM];
__device__ ull   g_Td[NK][DIM * 32 * 4]; // [i][lane]{Mlo_dup,Mhi_dup,Plo_dup,Phi_dup}
__device__ float g_thr[EH];
__device__ unsigned char g_act[NK][EH];
__device__ int   g_kedge[E_NUM];
__device__ float g_aedge[E_NUM];
__device__ int   g_used[NK];
__device__ int   g_slotmap[NK];
__device__ int   g_slotk[MAXU];
__device__ int   g_usedlist[NK];
__device__ int   g_usedcnt;
__device__ int   g_nslots;
__device__ int   g_deg[N_TGT];
__device__ int   g_off[N_TGT];
__device__ int   g_cur[N_TGT];
__device__ uint2 g_ce[E_NUM];            // {word, float-bits a}
// weight tables (all lane-consecutive for coalesced LDG.128)
__device__ ull   g_W0q[IN_DIM * 32];     // ((i>>1)*32+j)*2+(i&1), j = output pair
__device__ ull   g_Wih_q[DIM * 3 * 64];  // paired-gate dup tables (ulonglong2 loads)
__device__ ull   g_Whh_q[DIM * 3 * 64];
__device__ ull   g_Wr_q[DIM * 64];
__device__ ull   g_W1q[DIM * 64];
__device__ ull   g_W2q[DIM * 64];

// ================= kA: zero + prep + setup (merged) ======================
__global__ __launch_bounds__(256) void kA(const float* __restrict__ W0,
                                          const float* __restrict__ Wih,
                                          const float* __restrict__ Whh,
                                          const float* __restrict__ Wr,
                                          const float* __restrict__ W1,
                                          const float* __restrict__ W2,
                                          const float* __restrict__ A1,
                                          const float* __restrict__ c1) {
    int b = blockIdx.x;
    int t = threadIdx.x;
    if (b < 79) {                               // zero
        int idx = b * 256 + t;
        if (idx < N_TGT) g_deg[idx] = 0;
        if (idx < NK)    g_used[idx] = 0;
        return;
    }
    if (b < 127) {                              // prep
        int idx = (b - 79) * 256 + t;
        if (idx < IN_DIM * 32) {                // W0 pairs: i 0..127, j 0..31
            int i = idx >> 5, j = idx & 31;
            float wa = W0[(2 * j) * IN_DIM + i];
            float wb = W0[(2 * j + 1) * IN_DIM + i];
            g_W0q[((i >> 1) * 32 + j) * 2 + (i & 1)] = pk2(wa, wb);
        }
        if (idx < DIM * G3) {
            int o = idx / G3, g = idx % G3;
            int l = g & 31, tt = g >> 5;
            int pos = ((o * 3 + (tt >> 1)) * 32 + l) * 2 + (tt & 1);
            float wi = Wih[g * DIM + o]; g_Wih_q[pos] = pk2(wi, wi);
            float wh = Whh[g * DIM + o]; g_Whh_q[pos] = pk2(wh, wh);
        }
        if (idx < DIM * DIM) {
            int i = idx / DIM, o = idx % DIM;
            int pos = (i * 32 + (o & 31)) * 2 + (o >> 5);
            float wr = Wr[i * DIM + o];  g_Wr_q[pos] = pk2(wr, wr);
            float w1 = W1[o * DIM + i];  g_W1q[pos] = pk2(w1, w1);
            float w2 = W2[o * DIM + i];  g_W2q[pos] = pk2(w2, w2);
        }
        return;
    }
    // setup (1 block, threads < 128)
    __shared__ float ts[EH], sorted[EH];
    if (t >= EH) return;
    int j = t;
    float s = A1[j];
    float c = c1[j];
    float th = (s != 0.0f) ? (-c / s) : 2.0e30f;
    ts[j] = th;
    __syncwarp();
    __syncthreads();
    int rank = 0;
    for (int k = 0; k < EH; k++) {
        float tk = ts[k];
        rank += (tk < th) || (tk == th && k < j);
    }
    sorted[rank] = th;
    __syncthreads();
    g_thr[j] = sorted[j];
    const float BIGT = 1.0e29f;
    for (int k = 0; k < NK; k++) {
        float left  = (k > 0)  ? sorted[k - 1] : -2.0e30f;
        float right = (k < EH) ? sorted[k]     :  2.0e30f;
        bool linf = (left <= -BIGT), rinf = (right >= BIGT);
        float rep;
        if (linf && rinf)      rep = 0.0f;
        else if (linf)         rep = right - 1.0f;
        else if (rinf)         rep = left + 1.0f;
        else                   rep = 0.5f * (left + right);
        g_act[k][j] = (s * rep + c > 0.0f) ? 1 : 0;
    }
}

// ================= kB: h0 + edgek (merged) ===============================
#define H0_BLOCKS (N_SRC / 32)   // 2500
__global__ __launch_bounds__(256) void kB(const float* __restrict__ x,
                                          const float* __restrict__ b0,
                                          const int* __restrict__ eids,
                                          const float* __restrict__ ew,
                                          const int* __restrict__ edst) {
    __shared__ float sthr[EH];
    if (blockIdx.x < H0_BLOCKS) {
        // ---- h0 = relu(x @ W0^T + b0), coalesced paired-weight version ----
        int j  = threadIdx.x & 31;          // output pair index
        int gq = threadIdx.x >> 5;
        int row0 = blockIdx.x * 32 + gq * 4;
        ull acc[4] = {0ull, 0ull, 0ull, 0ull};
#pragma unroll 4
        for (int ii = 0; ii < IN_DIM / 4; ii++) {
            float4 xv0 = *reinterpret_cast<const float4*>(x + (size_t)(row0 + 0) * IN_DIM + ii * 4);
            float4 xv1 = *reinterpret_cast<const float4*>(x + (size_t)(row0 + 1) * IN_DIM + ii * 4);
            float4 xv2 = *reinterpret_cast<const float4*>(x + (size_t)(row0 + 2) * IN_DIM + ii * 4);
            float4 xv3 = *reinterpret_cast<const float4*>(x + (size_t)(row0 + 3) * IN_DIM + ii * 4);
            ulonglong2 wA = *reinterpret_cast<const ulonglong2*>(g_W0q + ((ii * 2 + 0) * 32 + j) * 2);
            ulonglong2 wB = *reinterpret_cast<const ulonglong2*>(g_W0q + ((ii * 2 + 1) * 32 + j) * 2);
#define H0_STEP(comp, wv)                                          \
            {                                                      \
                FMA_X2(acc[0], pk2(xv0.comp, xv0.comp), wv, acc[0]);\
                FMA_X2(acc[1], pk2(xv1.comp, xv1.comp), wv, acc[1]);\
                FMA_X2(acc[2], pk2(xv2.comp, xv2.comp), wv, acc[2]);\
                FMA_X2(acc[3], pk2(xv3.comp, xv3.comp), wv, acc[3]);\
            }
            H0_STEP(x, wA.x) H0_STEP(y, wA.y) H0_STEP(z, wB.x) H0_STEP(w, wB.y)
#undef H0_STEP
        }
        float ba = b0[2 * j], bb = b0[2 * j + 1];
#pragma unroll
        for (int r = 0; r < 4; r++) {
            float lo, hi;
            upk(acc[r], lo, hi);
            float2 v;
            v.x = fmaxf(lo + ba, 0.0f);
            v.y = fmaxf(hi + bb, 0.0f);
            *reinterpret_cast<float2*>(g_h0 + (size_t)(row0 + r) * DIM + 2 * j) = v;
        }
    } else {
        if (threadIdx.x < EH) sthr[threadIdx.x] = g_thr[threadIdx.x];
        __syncthreads();
        int e = (blockIdx.x - H0_BLOCKS) * 256 + threadIdx.x;
        if (e >= E_NUM) return;
        float a = ew[eids[e]];
        int k = 0;
#pragma unroll
        for (int j = 0; j < EH; j++) k += (sthr[j] < a) ? 1 : 0;
        g_kedge[e] = k;
        g_aedge[e] = a;
        g_used[k]  = 1;
        atomicAdd(&g_deg[edst[e]], 1);
    }
}

// ================= kC: scan (block 0) + slots (block 1) ==================
__global__ __launch_bounds__(1024) void kC() {
    if (blockIdx.x == 0) {
        __shared__ int wsum[32];
        int t = threadIdx.x;
        int start = t * 20;
        int s = 0;
#pragma unroll
        for (int i = 0; i < 20; i++) {
            int idx = start + i;
            if (idx < N_TGT) s += g_deg[idx];
        }
        int lane = t & 31, wid = t >> 5;
        int v = s;
#pragma unroll
        for (int off = 1; off < 32; off <<= 1) {
            int n = __shfl_up_sync(0xffffffffu, v, off);
            if (lane >= off) v += n;
        }
        if (lane == 31) wsum[wid] = v;
        __syncthreads();
        if (wid == 0) {
            int w = wsum[lane];
#pragma unroll
            for (int off = 1; off < 32; off <<= 1) {
                int n = __shfl_up_sync(0xffffffffu, w, off);
                if (lane >= off) w += n;
            }
            wsum[lane] = w;
        }
        __syncthreads();
        int excl = (v - s) + ((wid > 0) ? wsum[wid - 1] : 0);
        int run = excl;
#pragma unroll
        for (int i = 0; i < 20; i++) {
            int idx = start + i;
            if (idx < N_TGT) {
                g_off[idx] = run;
                g_cur[idx] = run;
                run += g_deg[idx];
            }
        }
    } else {
        if (threadIdx.x == 0) {
            int ns = 0;
            for (int k = 0; k < NK; k++) {
                g_slotmap[k] = -1;
                if (g_used[k]) {
                    if (ns < MAXU) { g_slotmap[k] = ns; g_slotk[ns] = k; }
                    g_usedlist[ns] = k;
                    ns++;
                }
            }
            g_usedcnt = ns;
            g_nslots = (ns < MAXU) ? ns : MAXU;
        }
    }
}

// ================= kD: csr + tables (merged) =============================
#define CSR_BLOCKS 313
#define TB_Y 2
__global__ __launch_bounds__(256) void kD(const int* __restrict__ esrc,
                                          const int* __restrict__ edst,
                                          const float* __restrict__ A1,
                                          const float* __restrict__ c1,
                                          const float* __restrict__ A2,
                                          const float* __restrict__ c2) {
    __shared__ float hs[EH], h2s[EH];
    if (blockIdx.x < CSR_BLOCKS) {
        int e = blockIdx.x * 256 + threadIdx.x;
        if (e >= E_NUM) return;
        int dst = edst[e];
        int pos = atomicAdd(&g_cur[dst], 1);
        int k = g_kedge[e];
        int sm = g_slotmap[k];
        unsigned sc = (sm >= 0) ? (unsigned)sm : 7u;
        uint2 ce;
        ce.x = (unsigned)esrc[e] | ((unsigned)k << 17) | (sc << 25);
        ce.y = __float_as_uint(g_aedge[e]);
        g_ce[pos] = ce;
    } else {
        int bb = blockIdx.x - CSR_BLOCKS;
        int bx = bb & 511;
        int by = bb >> 9;
        int cnt = g_usedcnt;
        int t = threadIdx.x;
        for (int y = by; y < cnt; y += TB_Y) {
            int k = g_usedlist[y];
            __syncthreads();
            if (t < EH) {
                float a = g_act[k][t] ? 1.0f : 0.0f;
                hs[t]  = A1[t] * a;
                h2s[t] = c1[t] * a;
            }
            __syncthreads();
            int w = t >> 5, l = t & 31;
            int io = bx * 8 + w;
            const float4 av = *reinterpret_cast<const float4*>(A2 + (size_t)io * EH + l * 4);
            float m = av.x * hs[l * 4] + av.y * hs[l * 4 + 1] + av.z * hs[l * 4 + 2] + av.w * hs[l * 4 + 3];
            float p = av.x * h2s[l * 4] + av.y * h2s[l * 4 + 1] + av.z * h2s[l * 4 + 2] + av.w * h2s[l * 4 + 3];
#pragma unroll
            for (int off = 16; off > 0; off >>= 1) {
                m += __shfl_down_sync(0xffffffffu, m, off);
                p += __shfl_down_sync(0xffffffffu, p, off);
            }
            if (l == 0) {
                float pv = c2[io] + p;
                g_M[k][io] = m;
                g_P[k][io] = pv;
                int i = io >> 6, o = io & 63;
                int base = (i * 32 + (o & 31)) * 4 + (o >> 5);
                g_Td[k][base]     = pk2(m, m);
                g_Td[k][base + 2] = pk2(pv, pv);
            }
        }
    }
}

// ================= k_tail: gather+transform+conv+gi+GRU+head =============
__global__ __launch_bounds__(256, 2) void k_tail(const float* __restrict__ b_conv,
                                                 const float* __restrict__ b_ih,
                                                 const float* __restrict__ b_hh,
                                                 const float* __restrict__ b1,
                                                 const float* __restrict__ b2,
                                                 float* __restrict__ out) {
    __shared__ float st[8][64 * 16];
    int wid = threadIdx.x >> 5;
    int l   = threadIdx.x & 31;
    int gw  = (blockIdx.x * 256 + threadIdx.x) >> 5;
    int t0  = gw * 4;
    float* sw = st[wid];
    int ns = g_nslots;

    int offv[4], degv[4];
#pragma unroll
    for (int q = 0; q < 4; q++) { offv[q] = g_off[t0 + q]; degv[q] = g_deg[t0 + q]; }
    int dmax = max(max(degv[0], degv[1]), max(degv[2], degv[3]));

    // pair-layout sums: lane l holds dims (2l, 2l+1) packed
    ull S1p[MAXU][4], S0p[MAXU][4];
#pragma unroll
    for (int s = 0; s < MAXU; s++)
#pragma unroll
        for (int q = 0; q < 4; q++) { S1p[s][q] = 0ull; S0p[s][q] = 0ull; }
    float fbA[4] = {0, 0, 0, 0}, fbB[4] = {0, 0, 0, 0};

    // ---- gather: depth-2 meta, depth-1 xs software pipeline ----
    uint2 mA[4], mB[4];
    float2 xA[4];
#pragma unroll
    for (int q = 0; q < 4; q++) if (degv[q] > 0) mA[q] = __ldg(&g_ce[offv[q]]);
#pragma unroll
    for (int q = 0; q < 4; q++) if (degv[q] > 1) mB[q] = __ldg(&g_ce[offv[q] + 1]);
#pragma unroll
    for (int q = 0; q < 4; q++)
        if (degv[q] > 0) {
            int s = (int)(mA[q].x & 0x1FFFFu);
            xA[q] = __ldg(reinterpret_cast<const float2*>(g_h0 + (size_t)s * DIM + 2 * l));
        }
    for (int j = 0; j < dmax; j++) {
        uint2 mC[4]; float2 xB[4];
#pragma unroll
        for (int q = 0; q < 4; q++)
            if (j + 2 < degv[q]) mC[q] = __ldg(&g_ce[offv[q] + j + 2]);
#pragma unroll
        for (int q = 0; q < 4; q++)
            if (j + 1 < degv[q]) {
                int s = (int)(mB[q].x & 0x1FFFFu);
                xB[q] = __ldg(reinterpret_cast<const float2*>(g_h0 + (size_t)s * DIM + 2 * l));
            }
#pragma unroll
        for (int q = 0; q < 4; q++) {
            if (j < degv[q]) {
                unsigned w = mA[q].x;
                float a = __uint_as_float(mA[q].y);
                unsigned sc = w >> 25;
                ull xsp = pk2(xA[q].x, xA[q].y);
                ull axp;
                MUL_X2(axp, xsp, pk2(a, a));
#pragma unroll
                for (int s = 0; s < MAXU; s++) {
                    float sel = (sc == (unsigned)s) ? 1.0f : 0.0f;
                    ull selp = pk2(sel, sel);
                    FMA_X2(S1p[s][q], axp, selp, S1p[s][q]);
                    FMA_X2(S0p[s][q], xsp, selp, S0p[s][q]);
                }
                if (sc == 7u) {                  // exact fallback (rare)
                    int k = (int)((w >> 17) & 0xFFu);
                    const float* __restrict__ M = g_M[k];
                    const float* __restrict__ P = g_P[k];
#pragma unroll 8
                    for (int i = 0; i < DIM; i++) {
                        float xi  = __shfl_sync(0xffffffffu, (i & 1) ? xA[q].y : xA[q].x, i >> 1);
                        float axi = a * xi;
                        fbA[q] += axi * M[i * DIM + l]      + xi * P[i * DIM + l];
                        fbB[q] += axi * M[i * DIM + 32 + l] + xi * P[i * DIM + 32 + l];
                    }
                }
            }
        }
#pragma unroll
        for (int q = 0; q < 4; q++) { mA[q] = mB[q]; mB[q] = mC[q]; xA[q] = xB[q]; }
    }

    // ---- stage S dim-major: sw[dim*16 + s*8 + {S1:0..3, S0:4..7}] ----
#pragma unroll
    for (int s = 0; s < MAXU; s++) {
        float x1[4], y1[4], x0[4], y0[4];
#pragma unroll
        for (int q = 0; q < 4; q++) {
            upk(S1p[s][q], x1[q], y1[q]);
            upk(S0p[s][q], x0[q], y0[q]);
        }
        *reinterpret_cast<float4*>(sw + (2 * l) * 16 + s * 8)         = make_float4(x1[0], x1[1], x1[2], x1[3]);
        *reinterpret_cast<float4*>(sw + (2 * l) * 16 + s * 8 + 4)     = make_float4(x0[0], x0[1], x0[2], x0[3]);
        *reinterpret_cast<float4*>(sw + (2 * l + 1) * 16 + s * 8)     = make_float4(y1[0], y1[1], y1[2], y1[3]);
        *reinterpret_cast<float4*>(sw + (2 * l + 1) * 16 + s * 8 + 4) = make_float4(y0[0], y0[1], y0[2], y0[3]);
    }
    __syncwarp();

    // ---- transform (dup-packed tables, ull2 smem reads: mov-free) ----
    ull accA[2], accB[2];
    accA[0] = pk2(fbA[0], fbA[1]); accA[1] = pk2(fbA[2], fbA[3]);
    accB[0] = pk2(fbB[0], fbB[1]); accB[1] = pk2(fbB[2], fbB[3]);
#pragma unroll
    for (int s = 0; s < MAXU; s++) {
        if (s >= ns) break;
        const ulonglong2* __restrict__ Td = reinterpret_cast<const ulonglong2*>(g_Td[g_slotk[s]]);
#pragma unroll 4
        for (int i = 0; i < DIM; i++) {
            ulonglong2 sv1 = *reinterpret_cast<const ulonglong2*>(sw + i * 16 + s * 8);
            ulonglong2 sv0 = *reinterpret_cast<const ulonglong2*>(sw + i * 16 + s * 8 + 4);
            ulonglong2 tA = __ldg(&Td[(i * 32 + l) * 2]);     // {Mlo_dup, Mhi_dup}
            ulonglong2 tB = __ldg(&Td[(i * 32 + l) * 2 + 1]); // {Plo_dup, Phi_dup}
            FMA_X2(accA[0], sv1.x, tA.x, accA[0]);
            FMA_X2(accA[1], sv1.y, tA.x, accA[1]);
            FMA_X2(accA[0], sv0.x, tB.x, accA[0]);
            FMA_X2(accA[1], sv0.y, tB.x, accA[1]);
            FMA_X2(accB[0], sv1.x, tA.y, accB[0]);
            FMA_X2(accB[1], sv1.y, tA.y, accB[1]);
            FMA_X2(accB[0], sv0.x, tB.y, accB[0]);
            FMA_X2(accB[1], sv0.y, tB.y, accB[1]);
        }
    }

    // ---- divide by counts ----
    {
        float i0 = __fdividef(1.0f, fmaxf((float)degv[0], 1.0f));
        float i1 = __fdividef(1.0f, fmaxf((float)degv[1], 1.0f));
        float i2 = __fdividef(1.0f, fmaxf((float)degv[2], 1.0f));
        float i3 = __fdividef(1.0f, fmaxf((float)degv[3], 1.0f));
        float v0, v1;
        upk(accA[0], v0, v1); accA[0] = pk2(v0 * i0, v1 * i1);
        upk(accA[1], v0, v1); accA[1] = pk2(v0 * i2, v1 * i3);
        upk(accB[0], v0, v1); accB[0] = pk2(v0 * i0, v1 * i1);
        upk(accB[1], v0, v1); accB[1] = pk2(v0 * i2, v1 * i3);
    }

    // ---- x_tgt pair-load + dim-major staging + conv root matvec ----
    float2 xtp[4];
#pragma unroll
    for (int q = 0; q < 4; q++)
        xtp[q] = *reinterpret_cast<const float2*>(g_h0 + (size_t)(t0 + q) * DIM + 2 * l);
    __syncwarp();
    *reinterpret_cast<float4*>(sw + (2 * l) * 4)     = make_float4(xtp[0].x, xtp[1].x, xtp[2].x, xtp[3].x);
    *reinterpret_cast<float4*>(sw + (2 * l + 1) * 4) = make_float4(xtp[0].y, xtp[1].y, xtp[2].y, xtp[3].y);
    __syncwarp();
#pragma unroll 4
    for (int i = 0; i < DIM; i++) {
        ulonglong2 xv = *reinterpret_cast<const ulonglong2*>(sw + i * 4);
        ulonglong2 wv = *reinterpret_cast<const ulonglong2*>(g_Wr_q + (i * 32 + l) * 2);
        FMA_X2(accA[0], xv.x, wv.x, accA[0]); FMA_X2(accA[1], xv.y, wv.x, accA[1]);
        FMA_X2(accB[0], xv.x, wv.y, accB[0]); FMA_X2(accB[1], xv.y, wv.y, accB[1]);
    }
    // x_tgt in l/32+l layout (for GRU h-init), read back from dim-major smem
    float xt0[4], xt1[4];
    {
        float4 v = *reinterpret_cast<const float4*>(sw + l * 4);
        xt0[0] = v.x; xt0[1] = v.y; xt0[2] = v.z; xt0[3] = v.w;
        float4 u = *reinterpret_cast<const float4*>(sw + (32 + l) * 4);
        xt1[0] = u.x; xt1[1] = u.y; xt1[2] = u.z; xt1[3] = u.w;
    }
    // m = relu(acc + b_conv) in l/32+l layout
    float m0[4], m1[4];
    {
        float bc0 = b_conv[l], bc1 = b_conv[32 + l];
        float v0, v1;
        upk(accA[0], v0, v1); m0[0] = fmaxf(v0 + bc0, 0.0f); m0[1] = fmaxf(v1 + bc0, 0.0f);
        upk(accA[1], v0, v1); m0[2] = fmaxf(v0 + bc0, 0.0f); m0[3] = fmaxf(v1 + bc0, 0.0f);
        upk(accB[0], v0, v1); m1[0] = fmaxf(v0 + bc1, 0.0f); m1[1] = fmaxf(v1 + bc1, 0.0f);
        upk(accB[1], v0, v1); m1[2] = fmaxf(v0 + bc1, 0.0f); m1[3] = fmaxf(v1 + bc1, 0.0f);
    }

    // ---- gi = m @ W_ih^T + b_ih ----
    __syncwarp();
    *reinterpret_cast<float4*>(sw + l * 4)        = make_float4(m0[0], m0[1], m0[2], m0[3]);
    *reinterpret_cast<float4*>(sw + (32 + l) * 4) = make_float4(m1[0], m1[1], m1[2], m1[3]);
    __syncwarp();
    ull gip[6][2];
#pragma unroll
    for (int t = 0; t < 6; t++) { gip[t][0] = 0ull; gip[t][1] = 0ull; }
#pragma unroll 2
    for (int o = 0; o < DIM; o++) {
        ulonglong2 mvp = *reinterpret_cast<const ulonglong2*>(sw + o * 4);
#pragma unroll
        for (int tp = 0; tp < 3; tp++) {
            ulonglong2 wv = *reinterpret_cast<const ulonglong2*>(g_Wih_q + ((o * 3 + tp) * 32 + l) * 2);
            FMA_X2(gip[2 * tp][0],     mvp.x, wv.x, gip[2 * tp][0]);
            FMA_X2(gip[2 * tp][1],     mvp.y, wv.x, gip[2 * tp][1]);
            FMA_X2(gip[2 * tp + 1][0], mvp.x, wv.y, gip[2 * tp + 1][0]);
            FMA_X2(gip[2 * tp + 1][1], mvp.y, wv.y, gip[2 * tp + 1][1]);
        }
    }
    float gi[6][4];
#pragma unroll
    for (int t = 0; t < 6; t++) {
        float bi = b_ih[l + 32 * t];
        float v0, v1;
        upk(gip[t][0], v0, v1); gi[t][0] = v0 + bi; gi[t][1] = v1 + bi;
        upk(gip[t][1], v0, v1); gi[t][2] = v0 + bi; gi[t][3] = v1 + bi;
    }

    // ---- GRU x3 (h init = x_tgt) ----
    float h0r[4], h1r[4];
#pragma unroll
    for (int q = 0; q < 4; q++) { h0r[q] = xt0[q]; h1r[q] = xt1[q]; }
    float bh[6];
#pragma unroll
    for (int t = 0; t < 6; t++) bh[t] = b_hh[l + 32 * t];

    for (int step = 0; step < 3; step++) {
        __syncwarp();
        *reinterpret_cast<float4*>(sw + l * 4)        = make_float4(h0r[0], h0r[1], h0r[2], h0r[3]);
        *reinterpret_cast<float4*>(sw + (32 + l) * 4) = make_float4(h1r[0], h1r[1], h1r[2], h1r[3]);
        __syncwarp();
        ull ghp[6][2];
#pragma unroll
        for (int t = 0; t < 6; t++) {
            ghp[t][0] = pk2(bh[t], bh[t]);
            ghp[t][1] = ghp[t][0];
        }
#pragma unroll 2
        for (int i = 0; i < DIM; i++) {
            ulonglong2 hvp = *reinterpret_cast<const ulonglong2*>(sw + i * 4);
#pragma unroll
            for (int tp = 0; tp < 3; tp++) {
                ulonglong2 wv = *reinterpret_cast<const ulonglong2*>(g_Whh_q + ((i * 3 + tp) * 32 + l) * 2);
                FMA_X2(ghp[2 * tp][0],     hvp.x, wv.x, ghp[2 * tp][0]);
                FMA_X2(ghp[2 * tp][1],     hvp.y, wv.x, ghp[2 * tp][1]);
                FMA_X2(ghp[2 * tp + 1][0], hvp.x, wv.y, ghp[2 * tp + 1][0]);
                FMA_X2(ghp[2 * tp + 1][1], hvp.y, wv.y, ghp[2 * tp + 1][1]);
            }
        }
#pragma unroll
        for (int q = 0; q < 4; q++) {
            float ghv[6];
#pragma unroll
            for (int t = 0; t < 6; t++) {
                float lo, hi;
                upk(ghp[t][q >> 1], lo, hi);
                ghv[t] = (q & 1) ? hi : lo;
            }
            float rr0 = sigm(gi[0][q] + ghv[0]);
            float rr1 = sigm(gi[1][q] + ghv[1]);
            float zz0 = sigm(gi[2][q] + ghv[2]);
            float zz1 = sigm(gi[3][q] + ghv[3]);
            float nn0 = tanhx(gi[4][q] + rr0 * ghv[4]);
            float nn1 = tanhx(gi[5][q] + rr1 * ghv[5]);
            h0r[q] = (1.0f - zz0) * nn0 + zz0 * h0r[q];
            h1r[q] = (1.0f - zz1) * nn1 + zz1 * h1r[q];
        }
    }

    // ---- head layer 1: a = relu(h @ W1^T + b1) ----
    __syncwarp();
    *reinterpret_cast<float4*>(sw + l * 4)        = make_float4(h0r[0], h0r[1], h0r[2], h0r[3]);
    *reinterpret_cast<float4*>(sw + (32 + l) * 4) = make_float4(h1r[0], h1r[1], h1r[2], h1r[3]);
    __syncwarp();
    ull aA01 = 0ull, aA23 = 0ull, aB01 = 0ull, aB23 = 0ull;
#pragma unroll 4
    for (int i = 0; i < DIM; i++) {
        ulonglong2 hvp = *reinterpret_cast<const ulonglong2*>(sw + i * 4);
        ulonglong2 wv = *reinterpret_cast<const ulonglong2*>(g_W1q + (i * 32 + l) * 2);
        FMA_X2(aA01, hvp.x, wv.x, aA01); FMA_X2(aA23, hvp.y, wv.x, aA23);
        FMA_X2(aB01, hvp.x, wv.y, aB01); FMA_X2(aB23, hvp.y, wv.y, aB23);
    }
    float a0[4], a1[4];
    {
        float bb0 = b1[l], bb1 = b1[32 + l];
        float v0, v1;
        upk(aA01, v0, v1); a0[0] = fmaxf(v0 + bb0, 0.0f); a0[1] = fmaxf(v1 + bb0, 0.0f);
        upk(aA23, v0, v1); a0[2] = fmaxf(v0 + bb0, 0.0f); a0[3] = fmaxf(v1 + bb0, 0.0f);
        upk(aB01, v0, v1); a1[0] = fmaxf(v0 + bb1, 0.0f); a1[1] = fmaxf(v1 + bb1, 0.0f);
        upk(aB23, v0, v1); a1[2] = fmaxf(v0 + bb1, 0.0f); a1[3] = fmaxf(v1 + bb1, 0.0f);
    }

    // ---- head layer 2: out = a @ W2^T + b2 ----
    __syncwarp();
    *reinterpret_cast<float4*>(sw + l * 4)        = make_float4(a0[0], a0[1], a0[2], a0[3]);
    *reinterpret_cast<float4*>(sw + (32 + l) * 4) = make_float4(a1[0], a1[1], a1[2], a1[3]);
    __syncwarp();
    ull cA01 = 0ull, cA23 = 0ull, cB01 = 0ull, cB23 = 0ull;
#pragma unroll 4
    for (int i = 0; i < DIM; i++) {
        ulonglong2 avp = *reinterpret_cast<const ulonglong2*>(sw + i * 4);
        ulonglong2 wv = *reinterpret_cast<const ulonglong2*>(g_W2q + (i * 32 + l) * 2);
        FMA_X2(cA01, avp.x, wv.x, cA01); FMA_X2(cA23, avp.y, wv.x, cA23);
        FMA_X2(cB01, avp.x, wv.y, cB01); FMA_X2(cB23, avp.y, wv.y, cB23);
    }
    {
        float ob0 = b2[l], ob1 = b2[32 + l];
        float v0, v1;
        upk(cA01, v0, v1);
        out[(size_t)(t0 + 0) * DIM + l] = v0 + ob0;
        out[(size_t)(t0 + 1) * DIM + l] = v1 + ob0;
        upk(cA23, v0, v1);
        out[(size_t)(t0 + 2) * DIM + l] = v0 + ob0;
        out[(size_t)(t0 + 3) * DIM + l] = v1 + ob0;
        upk(cB01, v0, v1);
        out[(size_t)(t0 + 0) * DIM + 32 + l] = v0 + ob1;
        out[(size_t)(t0 + 1) * DIM + 32 + l] = v1 + ob1;
        upk(cB23, v0, v1);
        out[(size_t)(t0 + 2) * DIM + 32 + l] = v0 + ob1;
        out[(size_t)(t0 + 3) * DIM + 32 + l] = v1 + ob1;
    }
}

// ---------------- launch ---------------------------------------------------
extern "C" void kernel_launch(void* const* d_in, const int* in_sizes, int n_in,
                              void* d_out, int out_size) {
    const float* x        = (const float*)d_in[0];
    const int*   edge_src = (const int*)d_in[2];
    const int*   edge_dst = (const int*)d_in[3];
    const int*   edge_ids = (const int*)d_in[4];
    const float* edge_w   = (const float*)d_in[5];
    const float* W0       = (const float*)d_in[6];
    const float* b0       = (const float*)d_in[7];
    const float* A1       = (const float*)d_in[8];
    const float* c1       = (const float*)d_in[9];
    const float* A2       = (const float*)d_in[10];
    const float* c2       = (const float*)d_in[11];
    const float* W_root   = (const float*)d_in[12];
    const float* b_conv   = (const float*)d_in[13];
    const float* W_ih     = (const float*)d_in[14];
    const float* W_hh     = (const float*)d_in[15];
    const float* b_ih     = (const float*)d_in[16];
    const float* b_hh     = (const float*)d_in[17];
    const float* W1       = (const float*)d_in[18];
    const float* b1       = (const float*)d_in[19];
    const float* W2       = (const float*)d_in[20];
    const float* b2       = (const float*)d_in[21];
    float* out = (float*)d_out;

    kA<<<128, 256>>>(W0, W_ih, W_hh, W_root, W1, W2, A1, c1);
    kB<<<H0_BLOCKS + 313, 256>>>(x, b0, edge_ids, edge_w, edge_dst);
    kC<<<2, 1024>>>();
    kD<<<CSR_BLOCKS + 512 * TB_Y, 256>>>(edge_src, edge_dst, A1, c1, A2, c2);
    k_tail<<<N_TGT / 4 / 8, 256>>>(b_conv, b_ih, b_hh, b1, b2, out);
}

// round 17
// speedup vs baseline: 1.3671x; 1.0924x over previous
#include <cuda_runtime.h>
#include <math.h>

#define N_SRC  80000
#define N_TGT  20000
#define E_NUM  80000
#define IN_DIM 128
#define DIM    64
#define EH     128
#define G3     192
#define NK     129
#define MAXU   2

typedef unsigned long long ull;

__device__ __forceinline__ ull pk2(float lo, float hi) {
    ull r; asm("mov.b64 %0, {%1,%2};" : "=l"(r) : "f"(lo), "f"(hi)); return r;
}
__device__ __forceinline__ void upk(ull v, float& lo, float& hi) {
    asm("mov.b64 {%0,%1}, %2;" : "=f"(lo), "=f"(hi) : "l"(v));
}
#define FMA_X2(d, a, b, c) asm("fma.rn.f32x2 %0, %1, %2, %3;" : "=l"(d) : "l"(a), "l"(b), "l"(c))
#define MUL_X2(d, a, b)    asm("mul.rn.f32x2 %0, %1, %2;"     : "=l"(d) : "l"(a), "l"(b))

__device__ __forceinline__ float sigm(float x)  { return __fdividef(1.0f, 1.0f + __expf(-x)); }
__device__ __forceinline__ float tanhx(float x) { return 1.0f - __fdividef(2.0f, 1.0f + __expf(2.0f * x)); }

// ---------------- scratch ------------------------------------------------
__device__ float g_h0[N_SRC * DIM];
__device__ float g_M[NK][DIM * DIM];
__device__ float g_P[NK][DIM * DIM];
__device__ float g_T[NK][DIM * 128];     // packed: [i][lane] = {M_lo,M_hi,P_lo,P_hi}
__device__ float g_thr[EH];
__device__ unsigned char g_act[NK][EH];
__device__ int   g_kedge[E_NUM];
__device__ float g_aedge[E_NUM];
__device__ int   g_used[NK];
__device__ int   g_slotmap[NK];
__device__ int   g_slotk[MAXU];
__device__ int   g_usedlist[NK];
__device__ int   g_usedcnt;
__device__ int   g_nslots;
__device__ int   g_deg[N_TGT];
__device__ int   g_off[N_TGT];
__device__ int   g_cur[N_TGT];
__device__ uint2 g_ce[E_NUM];            // {word, float-bits a}
// weight tables (all lane-consecutive for coalesced LDG.128)
__device__ ull   g_W0q[IN_DIM * 32];     // ((i>>1)*32+j)*2+(i&1), j = output pair
__device__ ull   g_Wih_q[DIM * 3 * 64];  // paired-gate dup tables (ulonglong2 loads)
__device__ ull   g_Whh_q[DIM * 3 * 64];
__device__ ull   g_Wr_q[DIM * 64];
__device__ ull   g_W1q[DIM * 64];
__device__ ull   g_W2q[DIM * 64];

// ================= kA: zero + prep + setup (merged) ======================
__global__ __launch_bounds__(256) void kA(const float* __restrict__ W0,
                                          const float* __restrict__ Wih,
                                          const float* __restrict__ Whh,
                                          const float* __restrict__ Wr,
                                          const float* __restrict__ W1,
                                          const float* __restrict__ W2,
                                          const float* __restrict__ A1,
                                          const float* __restrict__ c1) {
    int b = blockIdx.x;
    int t = threadIdx.x;
    if (b < 79) {                               // zero
        int idx = b * 256 + t;
        if (idx < N_TGT) g_deg[idx] = 0;
        if (idx < NK)    g_used[idx] = 0;
        return;
    }
    if (b < 127) {                              // prep
        int idx = (b - 79) * 256 + t;
        if (idx < IN_DIM * 32) {                // W0 pairs: i 0..127, j 0..31
            int i = idx >> 5, j = idx & 31;
            float wa = W0[(2 * j) * IN_DIM + i];
            float wb = W0[(2 * j + 1) * IN_DIM + i];
            g_W0q[((i >> 1) * 32 + j) * 2 + (i & 1)] = pk2(wa, wb);
        }
        if (idx < DIM * G3) {
            int o = idx / G3, g = idx % G3;
            int l = g & 31, tt = g >> 5;
            int pos = ((o * 3 + (tt >> 1)) * 32 + l) * 2 + (tt & 1);
            float wi = Wih[g * DIM + o]; g_Wih_q[pos] = pk2(wi, wi);
            float wh = Whh[g * DIM + o]; g_Whh_q[pos] = pk2(wh, wh);
        }
        if (idx < DIM * DIM) {
            int i = idx / DIM, o = idx % DIM;
            int pos = (i * 32 + (o & 31)) * 2 + (o >> 5);
            float wr = Wr[i * DIM + o];  g_Wr_q[pos] = pk2(wr, wr);
            float w1 = W1[o * DIM + i];  g_W1q[pos] = pk2(w1, w1);
            float w2 = W2[o * DIM + i];  g_W2q[pos] = pk2(w2, w2);
        }
        return;
    }
    // setup (1 block, threads < 128)
    __shared__ float ts[EH], sorted[EH];
    if (t >= EH) return;
    int j = t;
    float s = A1[j];
    float c = c1[j];
    float th = (s != 0.0f) ? (-c / s) : 2.0e30f;
    ts[j] = th;
    __syncwarp();
    __syncthreads();
    int rank = 0;
    for (int k = 0; k < EH; k++) {
        float tk = ts[k];
        rank += (tk < th) || (tk == th && k < j);
    }
    sorted[rank] = th;
    __syncthreads();
    g_thr[j] = sorted[j];
    const float BIGT = 1.0e29f;
    for (int k = 0; k < NK; k++) {
        float left  = (k > 0)  ? sorted[k - 1] : -2.0e30f;
        float right = (k < EH) ? sorted[k]     :  2.0e30f;
        bool linf = (left <= -BIGT), rinf = (right >= BIGT);
        float rep;
        if (linf && rinf)      rep = 0.0f;
        else if (linf)         rep = right - 1.0f;
        else if (rinf)         rep = left + 1.0f;
        else                   rep = 0.5f * (left + right);
        g_act[k][j] = (s * rep + c > 0.0f) ? 1 : 0;
    }
}

// ================= kB: h0 + edgek (merged) ===============================
#define H0_BLOCKS (N_SRC / 32)   // 2500
__global__ __launch_bounds__(256) void kB(const float* __restrict__ x,
                                          const float* __restrict__ b0,
                                          const int* __restrict__ eids,
                                          const float* __restrict__ ew,
                                          const int* __restrict__ edst) {
    __shared__ float sthr[EH];
    if (blockIdx.x < H0_BLOCKS) {
        // ---- h0 = relu(x @ W0^T + b0), coalesced paired-weight version ----
        int j  = threadIdx.x & 31;          // output pair index
        int gq = threadIdx.x >> 5;
        int row0 = blockIdx.x * 32 + gq * 4;
        ull acc[4] = {0ull, 0ull, 0ull, 0ull};
#pragma unroll 4
        for (int ii = 0; ii < IN_DIM / 4; ii++) {
            float4 xv0 = *reinterpret_cast<const float4*>(x + (size_t)(row0 + 0) * IN_DIM + ii * 4);
            float4 xv1 = *reinterpret_cast<const float4*>(x + (size_t)(row0 + 1) * IN_DIM + ii * 4);
            float4 xv2 = *reinterpret_cast<const float4*>(x + (size_t)(row0 + 2) * IN_DIM + ii * 4);
            float4 xv3 = *reinterpret_cast<const float4*>(x + (size_t)(row0 + 3) * IN_DIM + ii * 4);
            ulonglong2 wA = *reinterpret_cast<const ulonglong2*>(g_W0q + ((ii * 2 + 0) * 32 + j) * 2);
            ulonglong2 wB = *reinterpret_cast<const ulonglong2*>(g_W0q + ((ii * 2 + 1) * 32 + j) * 2);
#define H0_STEP(comp, wv)                                          \
            {                                                      \
                FMA_X2(acc[0], pk2(xv0.comp, xv0.comp), wv, acc[0]);\
                FMA_X2(acc[1], pk2(xv1.comp, xv1.comp), wv, acc[1]);\
                FMA_X2(acc[2], pk2(xv2.comp, xv2.comp), wv, acc[2]);\
                FMA_X2(acc[3], pk2(xv3.comp, xv3.comp), wv, acc[3]);\
            }
            H0_STEP(x, wA.x) H0_STEP(y, wA.y) H0_STEP(z, wB.x) H0_STEP(w, wB.y)
#undef H0_STEP
        }
        float ba = b0[2 * j], bb = b0[2 * j + 1];
#pragma unroll
        for (int r = 0; r < 4; r++) {
            float lo, hi;
            upk(acc[r], lo, hi);
            float2 v;
            v.x = fmaxf(lo + ba, 0.0f);
            v.y = fmaxf(hi + bb, 0.0f);
            *reinterpret_cast<float2*>(g_h0 + (size_t)(row0 + r) * DIM + 2 * j) = v;
        }
    } else {
        if (threadIdx.x < EH) sthr[threadIdx.x] = g_thr[threadIdx.x];
        __syncthreads();
        int e = (blockIdx.x - H0_BLOCKS) * 256 + threadIdx.x;
        if (e >= E_NUM) return;
        float a = ew[eids[e]];
        int k = 0;
#pragma unroll
        for (int j = 0; j < EH; j++) k += (sthr[j] < a) ? 1 : 0;
        g_kedge[e] = k;
        g_aedge[e] = a;
        g_used[k]  = 1;
        atomicAdd(&g_deg[edst[e]], 1);
    }
}

// ================= kC: scan (block 0) + slots (block 1) ==================
__global__ __launch_bounds__(1024) void kC() {
    if (blockIdx.x == 0) {
        __shared__ int wsum[32];
        int t = threadIdx.x;
        int start = t * 20;
        int s = 0;
#pragma unroll
        for (int i = 0; i < 20; i++) {
            int idx = start + i;
            if (idx < N_TGT) s += g_deg[idx];
        }
        int lane = t & 31, wid = t >> 5;
        int v = s;
#pragma unroll
        for (int off = 1; off < 32; off <<= 1) {
            int n = __shfl_up_sync(0xffffffffu, v, off);
            if (lane >= off) v += n;
        }
        if (lane == 31) wsum[wid] = v;
        __syncthreads();
        if (wid == 0) {
            int w = wsum[lane];
#pragma unroll
            for (int off = 1; off < 32; off <<= 1) {
                int n = __shfl_up_sync(0xffffffffu, w, off);
                if (lane >= off) w += n;
            }
            wsum[lane] = w;
        }
        __syncthreads();
        int excl = (v - s) + ((wid > 0) ? wsum[wid - 1] : 0);
        int run = excl;
#pragma unroll
        for (int i = 0; i < 20; i++) {
            int idx = start + i;
            if (idx < N_TGT) {
                g_off[idx] = run;
                g_cur[idx] = run;
                run += g_deg[idx];
            }
        }
    } else {
        if (threadIdx.x == 0) {
            int ns = 0;
            for (int k = 0; k < NK; k++) {
                g_slotmap[k] = -1;
                if (g_used[k]) {
                    if (ns < MAXU) { g_slotmap[k] = ns; g_slotk[ns] = k; }
                    g_usedlist[ns] = k;
                    ns++;
                }
            }
            g_usedcnt = ns;
            g_nslots = (ns < MAXU) ? ns : MAXU;
        }
    }
}

// ================= kD: csr + tables (merged) =============================
#define CSR_BLOCKS 313
#define TB_Y 2
__global__ __launch_bounds__(256) void kD(const int* __restrict__ esrc,
                                          const int* __restrict__ edst,
                                          const float* __restrict__ A1,
                                          const float* __restrict__ c1,
                                          const float* __restrict__ A2,
                                          const float* __restrict__ c2) {
    __shared__ float hs[EH], h2s[EH];
    if (blockIdx.x < CSR_BLOCKS) {
        int e = blockIdx.x * 256 + threadIdx.x;
        if (e >= E_NUM) return;
        int dst = edst[e];
        int pos = atomicAdd(&g_cur[dst], 1);
        int k = g_kedge[e];
        int sm = g_slotmap[k];
        unsigned sc = (sm >= 0) ? (unsigned)sm : 7u;
        uint2 ce;
        ce.x = (unsigned)esrc[e] | ((unsigned)k << 17) | (sc << 25);
        ce.y = __float_as_uint(g_aedge[e]);
        g_ce[pos] = ce;
    } else {
        int bb = blockIdx.x - CSR_BLOCKS;
        int bx = bb & 511;
        int by = bb >> 9;
        int cnt = g_usedcnt;
        int t = threadIdx.x;
        for (int y = by; y < cnt; y += TB_Y) {
            int k = g_usedlist[y];
            __syncthreads();
            if (t < EH) {
                float a = g_act[k][t] ? 1.0f : 0.0f;
                hs[t]  = A1[t] * a;
                h2s[t] = c1[t] * a;
            }
            __syncthreads();
            int w = t >> 5, l = t & 31;
            int io = bx * 8 + w;
            const float4 av = *reinterpret_cast<const float4*>(A2 + (size_t)io * EH + l * 4);
            float m = av.x * hs[l * 4] + av.y * hs[l * 4 + 1] + av.z * hs[l * 4 + 2] + av.w * hs[l * 4 + 3];
            float p = av.x * h2s[l * 4] + av.y * h2s[l * 4 + 1] + av.z * h2s[l * 4 + 2] + av.w * h2s[l * 4 + 3];
#pragma unroll
            for (int off = 16; off > 0; off >>= 1) {
                m += __shfl_down_sync(0xffffffffu, m, off);
                p += __shfl_down_sync(0xffffffffu, p, off);
            }
            if (l == 0) {
                float pv = c2[io] + p;
                g_M[k][io] = m;
                g_P[k][io] = pv;
                int i = io >> 6, o = io & 63;
                int tb = (i * 32 + (o & 31)) * 4 + ((o >> 5) & 1);
                g_T[k][tb]     = m;     // M at +0/+1
                g_T[k][tb + 2] = pv;    // P at +2/+3
            }
        }
    }
}

// ================= k_tail: gather+transform+conv+gi+GRU+head =============
__global__ __launch_bounds__(256, 2) void k_tail(const float* __restrict__ b_conv,
                                                 const float* __restrict__ b_ih,
                                                 const float* __restrict__ b_hh,
                                                 const float* __restrict__ b1,
                                                 const float* __restrict__ b2,
                                                 float* __restrict__ out) {
    __shared__ float st[8][64 * 16];
    int wid = threadIdx.x >> 5;
    int l   = threadIdx.x & 31;
    int gw  = (blockIdx.x * 256 + threadIdx.x) >> 5;
    int t0  = gw * 4;
    float* sw = st[wid];
    int ns = g_nslots;

    int offv[4], degv[4];
#pragma unroll
    for (int q = 0; q < 4; q++) { offv[q] = g_off[t0 + q]; degv[q] = g_deg[t0 + q]; }
    int dmax = max(max(degv[0], degv[1]), max(degv[2], degv[3]));

    // pair-layout sums: lane l holds dims (2l, 2l+1) packed
    ull S1p[MAXU][4], S0p[MAXU][4];
#pragma unroll
    for (int s = 0; s < MAXU; s++)
#pragma unroll
        for (int q = 0; q < 4; q++) { S1p[s][q] = 0ull; S0p[s][q] = 0ull; }
    float fbA[4] = {0, 0, 0, 0}, fbB[4] = {0, 0, 0, 0};

    // ---- gather (no software pipeline; 16 warps/SM hide the latency) ----
    for (int j = 0; j < dmax; j++) {
#pragma unroll
        for (int q = 0; q < 4; q++) {
            if (j < degv[q]) {                   // warp-uniform predicate
                uint2 ce = __ldg(&g_ce[offv[q] + j]);
                unsigned w = ce.x;
                float a = __uint_as_float(ce.y);
                int src = (int)(w & 0x1FFFFu);
                unsigned sc = w >> 25;
                float2 xs = __ldg(reinterpret_cast<const float2*>(g_h0 + (size_t)src * DIM + 2 * l));
                ull xsp = pk2(xs.x, xs.y);
                ull axp;
                MUL_X2(axp, xsp, pk2(a, a));
#pragma unroll
                for (int s = 0; s < MAXU; s++) {
                    float sel = (sc == (unsigned)s) ? 1.0f : 0.0f;
                    ull selp = pk2(sel, sel);
                    FMA_X2(S1p[s][q], axp, selp, S1p[s][q]);
                    FMA_X2(S0p[s][q], xsp, selp, S0p[s][q]);
                }
                if (sc == 7u) {                  // exact fallback (rare)
                    int k = (int)((w >> 17) & 0xFFu);
                    const float* __restrict__ M = g_M[k];
                    const float* __restrict__ P = g_P[k];
#pragma unroll 8
                    for (int i = 0; i < DIM; i++) {
                        float xi  = __shfl_sync(0xffffffffu, (i & 1) ? xs.y : xs.x, i >> 1);
                        float axi = a * xi;
                        fbA[q] += axi * M[i * DIM + l]      + xi * P[i * DIM + l];
                        fbB[q] += axi * M[i * DIM + 32 + l] + xi * P[i * DIM + 32 + l];
                    }
                }
            }
        }
    }

    // ---- stage S dim-major: sw[dim*16 + s*8 + {S1:0..3, S0:4..7}] ----
#pragma unroll
    for (int s = 0; s < MAXU; s++) {
        float x1[4], y1[4], x0[4], y0[4];
#pragma unroll
        for (int q = 0; q < 4; q++) {
            upk(S1p[s][q], x1[q], y1[q]);
            upk(S0p[s][q], x0[q], y0[q]);
        }
        *reinterpret_cast<float4*>(sw + (2 * l) * 16 + s * 8)         = make_float4(x1[0], x1[1], x1[2], x1[3]);
        *reinterpret_cast<float4*>(sw + (2 * l) * 16 + s * 8 + 4)     = make_float4(x0[0], x0[1], x0[2], x0[3]);
        *reinterpret_cast<float4*>(sw + (2 * l + 1) * 16 + s * 8)     = make_float4(y1[0], y1[1], y1[2], y1[3]);
        *reinterpret_cast<float4*>(sw + (2 * l + 1) * 16 + s * 8 + 4) = make_float4(y0[0], y0[1], y0[2], y0[3]);
    }
    __syncwarp();

    // ---- transform (round-11 proven layout: 1 LDG.128 + dup movs) ----
    ull accA[2], accB[2];
    accA[0] = pk2(fbA[0], fbA[1]); accA[1] = pk2(fbA[2], fbA[3]);
    accB[0] = pk2(fbB[0], fbB[1]); accB[1] = pk2(fbB[2], fbB[3]);
#pragma unroll
    for (int s = 0; s < MAXU; s++) {
        if (s >= ns) break;
        const float4* __restrict__ Tk = reinterpret_cast<const float4*>(g_T[g_slotk[s]]);
#pragma unroll 4
        for (int i = 0; i < DIM; i++) {
            ulonglong2 sv1 = *reinterpret_cast<const ulonglong2*>(sw + i * 16 + s * 8);
            ulonglong2 sv0 = *reinterpret_cast<const ulonglong2*>(sw + i * 16 + s * 8 + 4);
            float4 tv  = __ldg(&Tk[i * 32 + l]);   // {M_lo, M_hi, P_lo, P_hi}
            FMA_X2(accA[0], sv1.x, pk2(tv.x, tv.x), accA[0]);
            FMA_X2(accA[1], sv1.y, pk2(tv.x, tv.x), accA[1]);
            FMA_X2(accA[0], sv0.x, pk2(tv.z, tv.z), accA[0]);
            FMA_X2(accA[1], sv0.y, pk2(tv.z, tv.z), accA[1]);
            FMA_X2(accB[0], sv1.x, pk2(tv.y, tv.y), accB[0]);
            FMA_X2(accB[1], sv1.y, pk2(tv.y, tv.y), accB[1]);
            FMA_X2(accB[0], sv0.x, pk2(tv.w, tv.w), accB[0]);
            FMA_X2(accB[1], sv0.y, pk2(tv.w, tv.w), accB[1]);
        }
    }

    // ---- divide by counts ----
    {
        float i0 = __fdividef(1.0f, fmaxf((float)degv[0], 1.0f));
        float i1 = __fdividef(1.0f, fmaxf((float)degv[1], 1.0f));
        float i2 = __fdividef(1.0f, fmaxf((float)degv[2], 1.0f));
        float i3 = __fdividef(1.0f, fmaxf((float)degv[3], 1.0f));
        float v0, v1;
        upk(accA[0], v0, v1); accA[0] = pk2(v0 * i0, v1 * i1);
        upk(accA[1], v0, v1); accA[1] = pk2(v0 * i2, v1 * i3);
        upk(accB[0], v0, v1); accB[0] = pk2(v0 * i0, v1 * i1);
        upk(accB[1], v0, v1); accB[1] = pk2(v0 * i2, v1 * i3);
    }

    // ---- x_tgt pair-load + dim-major staging + conv root matvec ----
    float2 xtp[4];
#pragma unroll
    for (int q = 0; q < 4; q++)
        xtp[q] = *reinterpret_cast<const float2*>(g_h0 + (size_t)(t0 + q) * DIM + 2 * l);
    __syncwarp();
    *reinterpret_cast<float4*>(sw + (2 * l) * 4)     = make_float4(xtp[0].x, xtp[1].x, xtp[2].x, xtp[3].x);
    *reinterpret_cast<float4*>(sw + (2 * l + 1) * 4) = make_float4(xtp[0].y, xtp[1].y, xtp[2].y, xtp[3].y);
    __syncwarp();
#pragma unroll 4
    for (int i = 0; i < DIM; i++) {
        ulonglong2 xv = *reinterpret_cast<const ulonglong2*>(sw + i * 4);
        ulonglong2 wv = *reinterpret_cast<const ulonglong2*>(g_Wr_q + (i * 32 + l) * 2);
        FMA_X2(accA[0], xv.x, wv.x, accA[0]); FMA_X2(accA[1], xv.y, wv.x, accA[1]);
        FMA_X2(accB[0], xv.x, wv.y, accB[0]); FMA_X2(accB[1], xv.y, wv.y, accB[1]);
    }
    // x_tgt in l/32+l layout (for GRU h-init), read back from dim-major smem
    float xt0[4], xt1[4];
    {
        float4 v = *reinterpret_cast<const float4*>(sw + l * 4);
        xt0[0] = v.x; xt0[1] = v.y; xt0[2] = v.z; xt0[3] = v.w;
        float4 u = *reinterpret_cast<const float4*>(sw + (32 + l) * 4);
        xt1[0] = u.x; xt1[1] = u.y; xt1[2] = u.z; xt1[3] = u.w;
    }
    // m = relu(acc + b_conv) in l/32+l layout
    float m0[4], m1[4];
    {
        float bc0 = b_conv[l], bc1 = b_conv[32 + l];
        float v0, v1;
        upk(accA[0], v0, v1); m0[0] = fmaxf(v0 + bc0, 0.0f); m0[1] = fmaxf(v1 + bc0, 0.0f);
        upk(accA[1], v0, v1); m0[2] = fmaxf(v0 + bc0, 0.0f); m0[3] = fmaxf(v1 + bc0, 0.0f);
        upk(accB[0], v0, v1); m1[0] = fmaxf(v0 + bc1, 0.0f); m1[1] = fmaxf(v1 + bc1, 0.0f);
        upk(accB[1], v0, v1); m1[2] = fmaxf(v0 + bc1, 0.0f); m1[3] = fmaxf(v1 + bc1, 0.0f);
    }

    // ---- gi = m @ W_ih^T + b_ih ----
    __syncwarp();
    *reinterpret_cast<float4*>(sw + l * 4)        = make_float4(m0[0], m0[1], m0[2], m0[3]);
    *reinterpret_cast<float4*>(sw + (32 + l) * 4) = make_float4(m1[0], m1[1], m1[2], m1[3]);
    __syncwarp();
    ull gip[6][2];
#pragma unroll
    for (int t = 0; t < 6; t++) { gip[t][0] = 0ull; gip[t][1] = 0ull; }
#pragma unroll 2
    for (int o = 0; o < DIM; o++) {
        ulonglong2 mvp = *reinterpret_cast<const ulonglong2*>(sw + o * 4);
#pragma unroll
        for (int tp = 0; tp < 3; tp++) {
            ulonglong2 wv = *reinterpret_cast<const ulonglong2*>(g_Wih_q + ((o * 3 + tp) * 32 + l) * 2);
            FMA_X2(gip[2 * tp][0],     mvp.x, wv.x, gip[2 * tp][0]);
            FMA_X2(gip[2 * tp][1],     mvp.y, wv.x, gip[2 * tp][1]);
            FMA_X2(gip[2 * tp + 1][0], mvp.x, wv.y, gip[2 * tp + 1][0]);
            FMA_X2(gip[2 * tp + 1][1], mvp.y, wv.y, gip[2 * tp + 1][1]);
        }
    }
    float gi[6][4];
#pragma unroll
    for (int t = 0; t < 6; t++) {
        float bi = b_ih[l + 32 * t];
        float v0, v1;
        upk(gip[t][0], v0, v1); gi[t][0] = v0 + bi; gi[t][1] = v1 + bi;
        upk(gip[t][1], v0, v1); gi[t][2] = v0 + bi; gi[t][3] = v1 + bi;
    }

    // ---- GRU x3 (h init = x_tgt) ----
    float h0r[4], h1r[4];
#pragma unroll
    for (int q = 0; q < 4; q++) { h0r[q] = xt0[q]; h1r[q] = xt1[q]; }
    float bh[6];
#pragma unroll
    for (int t = 0; t < 6; t++) bh[t] = b_hh[l + 32 * t];

    for (int step = 0; step < 3; step++) {
        __syncwarp();
        *reinterpret_cast<float4*>(sw + l * 4)        = make_float4(h0r[0], h0r[1], h0r[2], h0r[3]);
        *reinterpret_cast<float4*>(sw + (32 + l) * 4) = make_float4(h1r[0], h1r[1], h1r[2], h1r[3]);
        __syncwarp();
        ull ghp[6][2];
#pragma unroll
        for (int t = 0; t < 6; t++) {
            ghp[t][0] = pk2(bh[t], bh[t]);
            ghp[t][1] = ghp[t][0];
        }
#pragma unroll 2
        for (int i = 0; i < DIM; i++) {
            ulonglong2 hvp = *reinterpret_cast<const ulonglong2*>(sw + i * 4);
#pragma unroll
            for (int tp = 0; tp < 3; tp++) {
                ulonglong2 wv = *reinterpret_cast<const ulonglong2*>(g_Whh_q + ((i * 3 + tp) * 32 + l) * 2);
                FMA_X2(ghp[2 * tp][0],     hvp.x, wv.x, ghp[2 * tp][0]);
                FMA_X2(ghp[2 * tp][1],     hvp.y, wv.x, ghp[2 * tp][1]);
                FMA_X2(ghp[2 * tp + 1][0], hvp.x, wv.y, ghp[2 * tp + 1][0]);
                FMA_X2(ghp[2 * tp + 1][1], hvp.y, wv.y, ghp[2 * tp + 1][1]);
            }
        }
#pragma unroll
        for (int q = 0; q < 4; q++) {
            float ghv[6];
#pragma unroll
            for (int t = 0; t < 6; t++) {
                float lo, hi;
                upk(ghp[t][q >> 1], lo, hi);
                ghv[t] = (q & 1) ? hi : lo;
            }
            float rr0 = sigm(gi[0][q] + ghv[0]);
            float rr1 = sigm(gi[1][q] + ghv[1]);
            float zz0 = sigm(gi[2][q] + ghv[2]);
            float zz1 = sigm(gi[3][q] + ghv[3]);
            float nn0 = tanhx(gi[4][q] + rr0 * ghv[4]);
            float nn1 = tanhx(gi[5][q] + rr1 * ghv[5]);
            h0r[q] = (1.0f - zz0) * nn0 + zz0 * h0r[q];
            h1r[q] = (1.0f - zz1) * nn1 + zz1 * h1r[q];
        }
    }

    // ---- head layer 1: a = relu(h @ W1^T + b1) ----
    __syncwarp();
    *reinterpret_cast<float4*>(sw + l * 4)        = make_float4(h0r[0], h0r[1], h0r[2], h0r[3]);
    *reinterpret_cast<float4*>(sw + (32 + l) * 4) = make_float4(h1r[0], h1r[1], h1r[2], h1r[3]);
    __syncwarp();
    ull aA01 = 0ull, aA23 = 0ull, aB01 = 0ull, aB23 = 0ull;
#pragma unroll 4
    for (int i = 0; i < DIM; i++) {
        ulonglong2 hvp = *reinterpret_cast<const ulonglong2*>(sw + i * 4);
        ulonglong2 wv = *reinterpret_cast<const ulonglong2*>(g_W1q + (i * 32 + l) * 2);
        FMA_X2(aA01, hvp.x, wv.x, aA01); FMA_X2(aA23, hvp.y, wv.x, aA23);
        FMA_X2(aB01, hvp.x, wv.y, aB01); FMA_X2(aB23, hvp.y, wv.y, aB23);
    }
    float a0[4], a1[4];
    {
        float bb0 = b1[l], bb1 = b1[32 + l];
        float v0, v1;
        upk(aA01, v0, v1); a0[0] = fmaxf(v0 + bb0, 0.0f); a0[1] = fmaxf(v1 + bb0, 0.0f);
        upk(aA23, v0, v1); a0[2] = fmaxf(v0 + bb0, 0.0f); a0[3] = fmaxf(v1 + bb0, 0.0f);
        upk(aB01, v0, v1); a1[0] = fmaxf(v0 + bb1, 0.0f); a1[1] = fmaxf(v1 + bb1, 0.0f);
        upk(aB23, v0, v1); a1[2] = fmaxf(v0 + bb1, 0.0f); a1[3] = fmaxf(v1 + bb1, 0.0f);
    }

    // ---- head layer 2: out = a @ W2^T + b2 ----
    __syncwarp();
    *reinterpret_cast<float4*>(sw + l * 4)        = make_float4(a0[0], a0[1], a0[2], a0[3]);
    *reinterpret_cast<float4*>(sw + (32 + l) * 4) = make_float4(a1[0], a1[1], a1[2], a1[3]);
    __syncwarp();
    ull cA01 = 0ull, cA23 = 0ull, cB01 = 0ull, cB23 = 0ull;
#pragma unroll 4
    for (int i = 0; i < DIM; i++) {
        ulonglong2 avp = *reinterpret_cast<const ulonglong2*>(sw + i * 4);
        ulonglong2 wv = *reinterpret_cast<const ulonglong2*>(g_W2q + (i * 32 + l) * 2);
        FMA_X2(cA01, avp.x, wv.x, cA01); FMA_X2(cA23, avp.y, wv.x, cA23);
        FMA_X2(cB01, avp.x, wv.y, cB01); FMA_X2(cB23, avp.y, wv.y, cB23);
    }
    {
        float ob0 = b2[l], ob1 = b2[32 + l];
        float v0, v1;
        upk(cA01, v0, v1);
        out[(size_t)(t0 + 0) * DIM + l] = v0 + ob0;
        out[(size_t)(t0 + 1) * DIM + l] = v1 + ob0;
        upk(cA23, v0, v1);
        out[(size_t)(t0 + 2) * DIM + l] = v0 + ob0;
        out[(size_t)(t0 + 3) * DIM + l] = v1 + ob0;
        upk(cB01, v0, v1);
        out[(size_t)(t0 + 0) * DIM + 32 + l] = v0 + ob1;
        out[(size_t)(t0 + 1) * DIM + 32 + l] = v1 + ob1;
        upk(cB23, v0, v1);
        out[(size_t)(t0 + 2) * DIM + 32 + l] = v0 + ob1;
        out[(size_t)(t0 + 3) * DIM + 32 + l] = v1 + ob1;
    }
}

// ---------------- launch ---------------------------------------------------
extern "C" void kernel_launch(void* const* d_in, const int* in_sizes, int n_in,
                              void* d_out, int out_size) {
    const float* x        = (const float*)d_in[0];
    const int*   edge_src = (const int*)d_in[2];
    const int*   edge_dst = (const int*)d_in[3];
    const int*   edge_ids = (const int*)d_in[4];
    const float* edge_w   = (const float*)d_in[5];
    const float* W0       = (const float*)d_in[6];
    const float* b0       = (const float*)d_in[7];
    const float* A1       = (const float*)d_in[8];
    const float* c1       = (const float*)d_in[9];
    const float* A2       = (const float*)d_in[10];
    const float* c2       = (const float*)d_in[11];
    const float* W_root   = (const float*)d_in[12];
    const float* b_conv   = (const float*)d_in[13];
    const float* W_ih     = (const float*)d_in[14];
    const float* W_hh     = (const float*)d_in[15];
    const float* b_ih     = (const float*)d_in[16];
    const float* b_hh     = (const float*)d_in[17];
    const float* W1       = (const float*)d_in[18];
    const float* b1       = (const float*)d_in[19];
    const float* W2       = (const float*)d_in[20];
    const float* b2       = (const float*)d_in[21];
    float* out = (float*)d_out;

    kA<<<128, 256>>>(W0, W_ih, W_hh, W_root, W1, W2, A1, c1);
    kB<<<H0_BLOCKS + 313, 256>>>(x, b0, edge_ids, edge_w, edge_dst);
    kC<<<2, 1024>>>();
    kD<<<CSR_BLOCKS + 512 * TB_Y, 256>>>(edge_src, edge_dst, A1, c1, A2, c2);
    k_tail<<<N_TGT / 4 / 8, 256>>>(b_conv, b_ih, b_hh, b1, b2, out);
}